// round 6
// baseline (speedup 1.0000x reference)
#include <cuda_runtime.h>
#include <cstdint>

// Problem constants (fixed shapes per reference)
#define C_DIM   1024
#define H_DIM   128
#define W_DIM   128
#define NROIS   256
#define NPATCH_TOT 1024                // 4 patches * 256 rois
#define THREADS 256
#define SEGS    4                      // column-scan segments (32 rows each)
#define SEG_H   (H_DIM / SEGS)

// Dynamic smem: tile (128*128) + cum (4*128)
#define SMEM_FLOATS (H_DIM * W_DIM + SEGS * W_DIM)
#define SMEM_BYTES  (SMEM_FLOATS * (int)sizeof(float))

// Channel-major intermediate: tmp[c][n]. Static device scratch (no allocs).
__device__ float g_tmp[C_DIM * NPATCH_TOT];

__global__ __launch_bounds__(THREADS, 3)
void roi_pool_sat_kernel(const float* __restrict__ fm,
                         const float* __restrict__ roi) {
    extern __shared__ float smem[];
    float* tile = smem;                  // [H][W] SAT workspace
    float* cum  = smem + H_DIM * W_DIM;  // [SEGS][W] exclusive col-seg bases

    const int tid  = threadIdx.x;
    const int lane = tid & 31;
    const int warp = tid >> 5;
    const int c    = blockIdx.x;

    // ---- Per-thread ROI -> shared 3x3 corner grid, in registers ----
    // Thread tid owns ROI r = tid (n = tid + 256k => r = n & 255 = tid).
    // The 2x2 patches of one ROI share corner coords: a 3x3 grid.
    // Match JAX op order exactly: wstep = (xmax-xmin)/2 (exact halving),
    // x_i = round(xmin + i*wstep) with left-assoc rn adds, no FMA
    // (__fmul_rn/__fadd_rn forbid contraction). rintf == jnp.round
    // (both round-half-to-even). i=0: 0*w=0, xmin+0=xmin exact.
    // i=1: 1*w=w exact.
    int X[3], Y[3];
    {
        const float4 rb = reinterpret_cast<const float4*>(roi)[tid];
        const float wstep = __fmul_rn(__fadd_rn(rb.z, -rb.x), 0.5f);
        const float hstep = __fmul_rn(__fadd_rn(rb.w, -rb.y), 0.5f);
        const float ax1 = __fadd_rn(rb.x, wstep);
        const float ay1 = __fadd_rn(rb.y, hstep);
        X[0] = (int)rintf(rb.x);
        X[1] = (int)rintf(ax1);
        X[2] = (int)rintf(__fadd_rn(ax1, wstep));
        Y[0] = (int)rintf(rb.y);
        Y[1] = (int)rintf(ay1);
        Y[2] = (int)rintf(__fadd_rn(ay1, hstep));
    }

    const float* plane = fm + (size_t)c * (H_DIM * W_DIM);

    // ---- Row-wise inclusive prefix sums: warp per row, 16 rows/warp ----
    // Lane holds 4 consecutive elements; in-thread scan + warp shuffle scan.
    // The 16 LDG.128 across j are independent -> deep MLP in the DRAM phase.
    #pragma unroll
    for (int j = 0; j < H_DIM / 8; j++) {
        const int r = warp * (H_DIM / 8) + j;
        float4 v = reinterpret_cast<const float4*>(plane + r * W_DIM)[lane];
        float s0 = v.x;
        float s1 = s0 + v.y;
        float s2 = s1 + v.z;
        float s3 = s2 + v.w;
        float x = s3;
        #pragma unroll
        for (int off = 1; off < 32; off <<= 1) {
            float y = __shfl_up_sync(0xffffffffu, x, off);
            if (lane >= off) x += y;
        }
        const float e = x - s3;   // exclusive prefix of this lane's chunk
        float4 o = make_float4(e + s0, e + s1, e + s2, e + s3);
        reinterpret_cast<float4*>(tile + r * W_DIM)[lane] = o;
    }
    __syncthreads();

    // ---- Column-wise LOCAL prefix sums: thread per (col-pair, segment) ----
    // 64 float2 column-pairs x 4 segments of 32 rows = 256 threads, all
    // active, conflict-free LDS.64/STS.64, 32-long serial FADD chains.
    {
        float2* tile2 = reinterpret_cast<float2*>(tile);
        const int q = tid & 63;          // column pair
        const int s = tid >> 6;          // segment 0..3
        float2 acc = make_float2(0.0f, 0.0f);
        #pragma unroll 8
        for (int h = s * SEG_H; h < (s + 1) * SEG_H; h++) {
            float2 v = tile2[h * (W_DIM / 2) + q];
            acc.x += v.x;
            acc.y += v.y;
            tile2[h * (W_DIM / 2) + q] = acc;
        }
        reinterpret_cast<float2*>(cum)[s * (W_DIM / 2) + q] = acc; // seg totals
    }
    __syncthreads();

    // ---- Convert segment totals to exclusive cumulative bases ----
    // Thread per column-pair (128 threads carry float2; rest idle briefly).
    if (tid < W_DIM / 2) {
        float2* cum2 = reinterpret_cast<float2*>(cum);
        const float2 t0 = cum2[0 * (W_DIM / 2) + tid];
        const float2 t1 = cum2[1 * (W_DIM / 2) + tid];
        const float2 t2 = cum2[2 * (W_DIM / 2) + tid];
        cum2[0 * (W_DIM / 2) + tid] = make_float2(0.0f, 0.0f);
        cum2[1 * (W_DIM / 2) + tid] = t0;
        cum2[2 * (W_DIM / 2) + tid] = make_float2(t0.x + t1.x, t0.y + t1.y);
        cum2[3 * (W_DIM / 2) + tid] = make_float2(t0.x + t1.x + t2.x,
                                                  t0.y + t1.y + t2.y);
    }
    __syncthreads();

    // ---- Gather: 3x3 shared SAT corner grid per ROI ----
    // SAT(y,x) = tile[y][x] + cum[y>>5][x]; A[j][i] = SAT(Y[j]-1, X[i]-1).
    float A[3][3];
    #pragma unroll
    for (int j = 0; j < 3; j++) {
        #pragma unroll
        for (int i = 0; i < 3; i++) {
            const int y = Y[j] - 1;
            const int x = X[i] - 1;
            float v = 0.0f;
            if (y >= 0 && x >= 0)
                v = tile[y * W_DIM + x] + cum[(y >> 5) * W_DIM + x];
            A[j][i] = v;
        }
    }

    // patch pi = iy*2 + ix ; n = pi*NROIS + tid (reference reshape order)
    float* dst = g_tmp + (size_t)c * NPATCH_TOT + tid;
    #pragma unroll
    for (int iy = 0; iy < 2; iy++) {
        #pragma unroll
        for (int ix = 0; ix < 2; ix++) {
            const float s = (A[iy + 1][ix + 1] - A[iy][ix + 1])
                          - (A[iy + 1][ix]     - A[iy][ix]);
            const float cnt = (float)((Y[iy + 1] - Y[iy]) * (X[ix + 1] - X[ix]));
            dst[(iy * 2 + ix) * NROIS] = s / fmaxf(cnt, 1.0f);
        }
    }
}

// ---- Transpose g_tmp[c][n] -> out[n][c], 32x32 smem tiles ----
__global__ __launch_bounds__(256)
void transpose_kernel(float* __restrict__ out) {
    __shared__ float t[32][33];
    const int bx = blockIdx.x * 32;   // n-tile origin (source col)
    const int by = blockIdx.y * 32;   // c-tile origin (source row)
    const int tx = threadIdx.x;       // 0..31
    const int ty = threadIdx.y;       // 0..7

    #pragma unroll
    for (int j = 0; j < 32; j += 8)
        t[ty + j][tx] = g_tmp[(size_t)(by + ty + j) * NPATCH_TOT + (bx + tx)];
    __syncthreads();
    #pragma unroll
    for (int j = 0; j < 32; j += 8)
        out[(size_t)(bx + ty + j) * C_DIM + (by + tx)] = t[tx][ty + j];
}

extern "C" void kernel_launch(void* const* d_in, const int* in_sizes, int n_in,
                              void* d_out, int out_size) {
    (void)in_sizes; (void)n_in; (void)out_size;
    const float* fm  = (const float*)d_in[0];   // feature_map (1024,128,128) f32
    const float* roi = (const float*)d_in[1];   // roi_batch (256,4) f32
    float* out = (float*)d_out;                 // (1024, 1024, 1, 1) f32

    // Host-side attrs (idempotent, not stream ops -> capture-safe).
    // Carveout 100%: guarantee the 3 x 67.6 KB blocks/SM the design assumes.
    cudaFuncSetAttribute(roi_pool_sat_kernel,
                         cudaFuncAttributeMaxDynamicSharedMemorySize, SMEM_BYTES);
    cudaFuncSetAttribute(roi_pool_sat_kernel,
                         cudaFuncAttributePreferredSharedMemoryCarveout, 100);

    roi_pool_sat_kernel<<<C_DIM, THREADS, SMEM_BYTES>>>(fm, roi);

    dim3 tgrid(NPATCH_TOT / 32, C_DIM / 32);
    dim3 tblk(32, 8);
    transpose_kernel<<<tgrid, tblk>>>(out);
}